// round 13
// baseline (speedup 1.0000x reference)
#include <cuda_runtime.h>
#include <cuda_bf16.h>
#include <cstdint>

// B=512, H=8, C=8192.
//   loss = -sum_{b,c} w'[c] * max(lg2(t ? p : 1-p), -100/ln2)
//   w'[c] = (ln2/C) * sum_h lam[h]*La[h,c]
// Kernel A (PDL-overlapped): computes w into g_w4, zeroes out.
// Kernel B: 512 blocks x 256 thr, 2 chunks x 4 float4-pairs, front-batched
// LDG.128, deferred-w.
// Log batching v2: ONE lg2 per component per thread (product of all 8
// samples). Per-element fixup at x < 2^-15 keeps the product normal
// ((2^-15)^8 = 2^-120 > 2^-126) and gives exact torch clamp semantics for
// x == 0 via fmaxf(log2 x, -144.27). x = |p + t - 1| (binary t).

#define B_DIM 512
#define H_DIM 8
#define C_DIM 8192
#define C4 (C_DIM / 4)                // 2048
#define NT 131072                     // total threads in kernel B
#define NBLOCKS (NT / 256)            // 512

#define LOG2_CLAMP (-144.26950408889634f)   // -100 / ln2
#define LN2 (0.6931471805599453f)
#define X_TINY 3.0517578125e-05f            // 2^-15

__device__ float g_w4[C_DIM];         // per-class weight * ln2 / C

// ---------------------------------------------------------------------------
// Kernel A: trigger B immediately, then compute w and zero the output.
// ---------------------------------------------------------------------------
__global__ void multibce_weights_kernel(const float* __restrict__ La,
                                        const float* __restrict__ lam,
                                        float* __restrict__ out) {
    cudaTriggerProgrammaticLaunchCompletion();
    int c = blockIdx.x * blockDim.x + threadIdx.x;
    if (c < C_DIM) {
        float s = 0.0f;
#pragma unroll
        for (int h = 0; h < H_DIM; ++h) {
            s = fmaf(lam[h], La[h * C_DIM + c], s);
        }
        g_w4[c] = s * (LN2 / (float)C_DIM);
    }
    if (c == 0) out[0] = 0.0f;
}

// ---------------------------------------------------------------------------
// Kernel B
// ---------------------------------------------------------------------------
// x = t ? p : 1-p = |p + t - 1| for binary t. Rare tiny x (incl. exact 0)
// is logged individually (clamped) and removed from the product.
__device__ __forceinline__ float xf(float p, float t, float& s) {
    float x = fabsf(p + t - 1.0f);
    if (x < X_TINY) {                         // rare: ~3e-5 per element
        s += fmaxf(__log2f(x), LOG2_CLAMP);   // exact clamp semantics
        x = 1.0f;
    }
    return x;
}

__global__ void __launch_bounds__(256, 4)
multibce_reduce_kernel(const float4* __restrict__ yp,
                       const float4* __restrict__ yt,
                       float* __restrict__ out) {
    const int tid = blockIdx.x * 256 + threadIdx.x;

    float sx = 0.0f, sy = 0.0f, sz = 0.0f, sw = 0.0f;
    float prx = 1.0f, pry = 1.0f, prz = 1.0f, prw = 1.0f;

#pragma unroll 1
    for (int jc = 0; jc < 2; ++jc) {
        int base = tid + jc * 4 * NT;
        float4 p0 = yp[base];
        float4 p1 = yp[base + NT];
        float4 p2 = yp[base + 2 * NT];
        float4 p3 = yp[base + 3 * NT];
        float4 t0 = yt[base];
        float4 t1 = yt[base + NT];
        float4 t2 = yt[base + 2 * NT];
        float4 t3 = yt[base + 3 * NT];

        prx *= xf(p0.x, t0.x, sx) * xf(p1.x, t1.x, sx)
             * xf(p2.x, t2.x, sx) * xf(p3.x, t3.x, sx);
        pry *= xf(p0.y, t0.y, sy) * xf(p1.y, t1.y, sy)
             * xf(p2.y, t2.y, sy) * xf(p3.y, t3.y, sy);
        prz *= xf(p0.z, t0.z, sz) * xf(p1.z, t1.z, sz)
             * xf(p2.z, t2.z, sz) * xf(p3.z, t3.z, sz);
        prw *= xf(p0.w, t0.w, sw) * xf(p1.w, t1.w, sw)
             * xf(p2.w, t2.w, sw) * xf(p3.w, t3.w, sw);
    }

    // One MUFU per component.
    sx += __log2f(prx);
    sy += __log2f(pry);
    sz += __log2f(prz);
    sw += __log2f(prw);

    // Wait for kernel A, then apply weights.
    cudaGridDependencySynchronize();
    float4 w = reinterpret_cast<const float4*>(g_w4)[tid & (C4 - 1)];
    float acc = fmaf(w.x, sx, fmaf(w.y, sy, fmaf(w.z, sz, w.w * sw)));

    // warp reduce
#pragma unroll
    for (int o = 16; o > 0; o >>= 1)
        acc += __shfl_xor_sync(0xFFFFFFFFu, acc, o);

    // block reduce
    __shared__ float smem[8];
    int lane = threadIdx.x & 31;
    int warp = threadIdx.x >> 5;
    if (lane == 0) smem[warp] = acc;
    __syncthreads();
    if (warp == 0) {
        acc = (lane < 8) ? smem[lane] : 0.0f;
#pragma unroll
        for (int o = 4; o > 0; o >>= 1)
            acc += __shfl_xor_sync(0xFFFFFFFFu, acc, o);
        if (lane == 0) atomicAdd(out, -acc);   // loss = -sum
    }
}

// ---------------------------------------------------------------------------
extern "C" void kernel_launch(void* const* d_in, const int* in_sizes, int n_in,
                              void* d_out, int out_size) {
    const float* y_pred = (const float*)d_in[0];
    const float* y_true = (const float*)d_in[1];
    const float* La     = (const float*)d_in[2];
    const float* lam    = (const float*)d_in[3];
    float* out = (float*)d_out;

    multibce_weights_kernel<<<(C_DIM + 255) / 256, 256>>>(La, lam, out);

    cudaLaunchConfig_t cfg = {};
    cfg.gridDim  = dim3(NBLOCKS);
    cfg.blockDim = dim3(256);
    cfg.dynamicSmemBytes = 0;
    cfg.stream = 0;
    cudaLaunchAttribute attr[1];
    attr[0].id = cudaLaunchAttributeProgrammaticStreamSerialization;
    attr[0].val.programmaticStreamSerializationAllowed = 1;
    cfg.attrs = attr;
    cfg.numAttrs = 1;
    cudaLaunchKernelEx(&cfg, multibce_reduce_kernel,
                       (const float4*)y_pred, (const float4*)y_true, out);
}

// round 15
// speedup vs baseline: 1.2536x; 1.2536x over previous
#include <cuda_runtime.h>
#include <cuda_bf16.h>
#include <cstdint>

// B=512, H=8, C=8192.
//   loss = -sum_{b,c} w'[c] * max(lg2(t ? p : 1-p), -100/ln2)
//   w'[c] = (ln2/C) * sum_h lam[h]*La[h,c]
// Kernel A (PDL-overlapped): computes w into g_w4, zeroes out.
// Kernel B: 512 blocks x 256 thr, 2 chunks x 4 float4-pairs, front-batched
// LDG.128, deferred-w, log batching (one lg2 per 4 elements).
// Branch-free element op: x = max(|p + t - 1|, 2^-30). Identity for every
// realizable nonzero x (>= 2^-24); a hypothetical exact zero contributes
// -30*ln2 instead of -100 (abs err ~0.02 on an O(1e3) sum -> rel ~2e-5).
// Per element: FADD + FMNMX(|.|) + FMUL. No FSETP/branches (R13 regression).

#define B_DIM 512
#define H_DIM 8
#define C_DIM 8192
#define C4 (C_DIM / 4)                // 2048
#define NT 131072                     // total threads in kernel B
#define NBLOCKS (NT / 256)            // 512

#define LN2 (0.6931471805599453f)
#define X_CLAMP 9.313225746154785e-10f   // 2^-30

__device__ float g_w4[C_DIM];         // per-class weight * ln2 / C

// ---------------------------------------------------------------------------
// Kernel A: trigger B immediately, then compute w and zero the output.
// ---------------------------------------------------------------------------
__global__ void multibce_weights_kernel(const float* __restrict__ La,
                                        const float* __restrict__ lam,
                                        float* __restrict__ out) {
    cudaTriggerProgrammaticLaunchCompletion();
    int c = blockIdx.x * blockDim.x + threadIdx.x;
    if (c < C_DIM) {
        float s = 0.0f;
#pragma unroll
        for (int h = 0; h < H_DIM; ++h) {
            s = fmaf(lam[h], La[h * C_DIM + c], s);
        }
        g_w4[c] = s * (LN2 / (float)C_DIM);
    }
    if (c == 0) out[0] = 0.0f;
}

// ---------------------------------------------------------------------------
// Kernel B
// ---------------------------------------------------------------------------
// x = t ? p : 1-p = |p + t - 1| for binary t; clamp below at 2^-30.
__device__ __forceinline__ float xc(float p, float t) {
    return fmaxf(fabsf(p + t - 1.0f), X_CLAMP);
}

__global__ void __launch_bounds__(256, 4)
multibce_reduce_kernel(const float4* __restrict__ yp,
                       const float4* __restrict__ yt,
                       float* __restrict__ out) {
    const int tid = blockIdx.x * 256 + threadIdx.x;

    float sx = 0.0f, sy = 0.0f, sz = 0.0f, sw = 0.0f;

#pragma unroll 1
    for (int jc = 0; jc < 2; ++jc) {
        int base = tid + jc * 4 * NT;
        float4 p0 = yp[base];
        float4 p1 = yp[base + NT];
        float4 p2 = yp[base + 2 * NT];
        float4 p3 = yp[base + 3 * NT];
        float4 t0 = yt[base];
        float4 t1 = yt[base + NT];
        float4 t2 = yt[base + 2 * NT];
        float4 t3 = yt[base + 3 * NT];

        float mx = xc(p0.x, t0.x) * xc(p1.x, t1.x)
                 * xc(p2.x, t2.x) * xc(p3.x, t3.x);
        float my = xc(p0.y, t0.y) * xc(p1.y, t1.y)
                 * xc(p2.y, t2.y) * xc(p3.y, t3.y);
        float mz = xc(p0.z, t0.z) * xc(p1.z, t1.z)
                 * xc(p2.z, t2.z) * xc(p3.z, t3.z);
        float mw = xc(p0.w, t0.w) * xc(p1.w, t1.w)
                 * xc(p2.w, t2.w) * xc(p3.w, t3.w);

        sx += __log2f(mx);
        sy += __log2f(my);
        sz += __log2f(mz);
        sw += __log2f(mw);
    }

    // Wait for kernel A, then apply weights.
    cudaGridDependencySynchronize();
    float4 w = reinterpret_cast<const float4*>(g_w4)[tid & (C4 - 1)];
    float acc = fmaf(w.x, sx, fmaf(w.y, sy, fmaf(w.z, sz, w.w * sw)));

    // warp reduce
#pragma unroll
    for (int o = 16; o > 0; o >>= 1)
        acc += __shfl_xor_sync(0xFFFFFFFFu, acc, o);

    // block reduce
    __shared__ float smem[8];
    int lane = threadIdx.x & 31;
    int warp = threadIdx.x >> 5;
    if (lane == 0) smem[warp] = acc;
    __syncthreads();
    if (warp == 0) {
        acc = (lane < 8) ? smem[lane] : 0.0f;
#pragma unroll
        for (int o = 4; o > 0; o >>= 1)
            acc += __shfl_xor_sync(0xFFFFFFFFu, acc, o);
        if (lane == 0) atomicAdd(out, -acc);   // loss = -sum
    }
}

// ---------------------------------------------------------------------------
extern "C" void kernel_launch(void* const* d_in, const int* in_sizes, int n_in,
                              void* d_out, int out_size) {
    const float* y_pred = (const float*)d_in[0];
    const float* y_true = (const float*)d_in[1];
    const float* La     = (const float*)d_in[2];
    const float* lam    = (const float*)d_in[3];
    float* out = (float*)d_out;

    multibce_weights_kernel<<<(C_DIM + 255) / 256, 256>>>(La, lam, out);

    cudaLaunchConfig_t cfg = {};
    cfg.gridDim  = dim3(NBLOCKS);
    cfg.blockDim = dim3(256);
    cfg.dynamicSmemBytes = 0;
    cfg.stream = 0;
    cudaLaunchAttribute attr[1];
    attr[0].id = cudaLaunchAttributeProgrammaticStreamSerialization;
    attr[0].val.programmaticStreamSerializationAllowed = 1;
    cfg.attrs = attr;
    cfg.numAttrs = 1;
    cudaLaunchKernelEx(&cfg, multibce_reduce_kernel,
                       (const float4*)y_pred, (const float4*)y_true, out);
}

// round 16
// speedup vs baseline: 1.3156x; 1.0494x over previous
#include <cuda_runtime.h>
#include <cuda_bf16.h>
#include <cstdint>

// B=512, H=8, C=8192.  (Final kernel — best measured config, R12)
//   loss = -sum_{b,c} w'[c] * max(lg2(t ? p : 1-p), -100/ln2)
//   w'[c] = (ln2/C) * sum_h lam[h]*La[h,c]
// Kernel A (PDL-overlapped): computes w into g_w4, zeroes out.
// Kernel B: 512 blocks x 256 thr, 2 chunks x 4 float4-pairs, front-batched
// LDG.128, deferred-w.
// Log batching: sum_j lg2(x_j) = lg2(prod of 4) per chunk -> 8 MUFU/thread.
// x==0 handled by cheap predicated rare path (substitute 1.0, count a
// -144.27 penalty) == torch clamp semantics exactly.

#define B_DIM 512
#define H_DIM 8
#define C_DIM 8192
#define C4 (C_DIM / 4)                // 2048
#define NT 131072                     // total threads in kernel B
#define NBLOCKS (NT / 256)            // 512

#define LOG2_CLAMP (-144.26950408889634f)   // -100 / ln2
#define LN2 (0.6931471805599453f)

__device__ float g_w4[C_DIM];         // per-class weight * ln2 / C

// ---------------------------------------------------------------------------
// Kernel A: trigger B immediately, then compute w and zero the output.
// ---------------------------------------------------------------------------
__global__ void multibce_weights_kernel(const float* __restrict__ La,
                                        const float* __restrict__ lam,
                                        float* __restrict__ out) {
    cudaTriggerProgrammaticLaunchCompletion();
    int c = blockIdx.x * blockDim.x + threadIdx.x;
    if (c < C_DIM) {
        float s = 0.0f;
#pragma unroll
        for (int h = 0; h < H_DIM; ++h) {
            s = fmaf(lam[h], La[h * C_DIM + c], s);
        }
        g_w4[c] = s * (LN2 / (float)C_DIM);
    }
    if (c == 0) out[0] = 0.0f;
}

// ---------------------------------------------------------------------------
// Kernel B
// ---------------------------------------------------------------------------
// x = t ? p : 1-p (exact for binary t). Nonzero x >= ~6e-8, so only exact
// zeros need the clamp; substitute 1.0 and count the -144.27 penalty.
__device__ __forceinline__ float xval(float p, float t, float& pen) {
    float x = fmaf(p, 2.0f * t - 1.0f, 1.0f - t);
    if (x < 1e-40f) { pen += 1.0f; x = 1.0f; }
    return x;
}

__global__ void __launch_bounds__(256, 4)
multibce_reduce_kernel(const float4* __restrict__ yp,
                       const float4* __restrict__ yt,
                       float* __restrict__ out) {
    const int tid = blockIdx.x * 256 + threadIdx.x;

    float sx = 0.0f, sy = 0.0f, sz = 0.0f, sw = 0.0f;
    float px = 0.0f, py = 0.0f, pz = 0.0f, pw = 0.0f;   // zero-penalty counts

#pragma unroll 1
    for (int jc = 0; jc < 2; ++jc) {
        int base = tid + jc * 4 * NT;
        float4 p0 = yp[base];
        float4 p1 = yp[base + NT];
        float4 p2 = yp[base + 2 * NT];
        float4 p3 = yp[base + 3 * NT];
        float4 t0 = yt[base];
        float4 t1 = yt[base + NT];
        float4 t2 = yt[base + 2 * NT];
        float4 t3 = yt[base + 3 * NT];

        float mx = xval(p0.x, t0.x, px) * xval(p1.x, t1.x, px)
                 * xval(p2.x, t2.x, px) * xval(p3.x, t3.x, px);
        float my = xval(p0.y, t0.y, py) * xval(p1.y, t1.y, py)
                 * xval(p2.y, t2.y, py) * xval(p3.y, t3.y, py);
        float mz = xval(p0.z, t0.z, pz) * xval(p1.z, t1.z, pz)
                 * xval(p2.z, t2.z, pz) * xval(p3.z, t3.z, pz);
        float mw = xval(p0.w, t0.w, pw) * xval(p1.w, t1.w, pw)
                 * xval(p2.w, t2.w, pw) * xval(p3.w, t3.w, pw);

        sx += __log2f(mx);
        sy += __log2f(my);
        sz += __log2f(mz);
        sw += __log2f(mw);
    }

    // Fold zero penalties (exact clamp contribution per zero element).
    sx = fmaf(px, LOG2_CLAMP, sx);
    sy = fmaf(py, LOG2_CLAMP, sy);
    sz = fmaf(pz, LOG2_CLAMP, sz);
    sw = fmaf(pw, LOG2_CLAMP, sw);

    // Wait for kernel A, then apply weights.
    cudaGridDependencySynchronize();
    float4 w = reinterpret_cast<const float4*>(g_w4)[tid & (C4 - 1)];
    float acc = fmaf(w.x, sx, fmaf(w.y, sy, fmaf(w.z, sz, w.w * sw)));

    // warp reduce
#pragma unroll
    for (int o = 16; o > 0; o >>= 1)
        acc += __shfl_xor_sync(0xFFFFFFFFu, acc, o);

    // block reduce
    __shared__ float smem[8];
    int lane = threadIdx.x & 31;
    int warp = threadIdx.x >> 5;
    if (lane == 0) smem[warp] = acc;
    __syncthreads();
    if (warp == 0) {
        acc = (lane < 8) ? smem[lane] : 0.0f;
#pragma unroll
        for (int o = 4; o > 0; o >>= 1)
            acc += __shfl_xor_sync(0xFFFFFFFFu, acc, o);
        if (lane == 0) atomicAdd(out, -acc);   // loss = -sum
    }
}

// ---------------------------------------------------------------------------
extern "C" void kernel_launch(void* const* d_in, const int* in_sizes, int n_in,
                              void* d_out, int out_size) {
    const float* y_pred = (const float*)d_in[0];
    const float* y_true = (const float*)d_in[1];
    const float* La     = (const float*)d_in[2];
    const float* lam    = (const float*)d_in[3];
    float* out = (float*)d_out;

    multibce_weights_kernel<<<(C_DIM + 255) / 256, 256>>>(La, lam, out);

    cudaLaunchConfig_t cfg = {};
    cfg.gridDim  = dim3(NBLOCKS);
    cfg.blockDim = dim3(256);
    cfg.dynamicSmemBytes = 0;
    cfg.stream = 0;
    cudaLaunchAttribute attr[1];
    attr[0].id = cudaLaunchAttributeProgrammaticStreamSerialization;
    attr[0].val.programmaticStreamSerializationAllowed = 1;
    cfg.attrs = attr;
    cfg.numAttrs = 1;
    cudaLaunchKernelEx(&cfg, multibce_reduce_kernel,
                       (const float4*)y_pred, (const float4*)y_true, out);
}